// round 13
// baseline (speedup 1.0000x reference)
#include <cuda_runtime.h>
#include <cuda_bf16.h>
#include <cstdint>

#define STX 132      // xs-kernel smem stride (proven)

// Scratch for x_s = x @ Wx^T + bx
__device__ float g_xs[65536 * 128];

__device__ __forceinline__ uint32_t f2tf32(float f) {
    uint32_t r; asm volatile("cvt.rna.tf32.f32 %0, %1;" : "=r"(r) : "f"(f)); return r;
}
__device__ __forceinline__ void mma_tf32_frag(float c[4], const uint32_t a[4], const uint32_t b[2]) {
    asm volatile(
        "mma.sync.aligned.m16n8k8.row.col.f32.tf32.tf32.f32 "
        "{%0,%1,%2,%3}, {%4,%5,%6,%7}, {%8,%9}, {%0,%1,%2,%3};"
        : "+f"(c[0]), "+f"(c[1]), "+f"(c[2]), "+f"(c[3])
        : "r"(a[0]), "r"(a[1]), "r"(a[2]), "r"(a[3]), "r"(b[0]), "r"(b[1]));
}
__device__ __forceinline__ void mma_bf16(float c[4], const uint32_t a[4], const uint32_t b[2]) {
    asm volatile(
        "mma.sync.aligned.m16n8k16.row.col.f32.bf16.bf16.f32 "
        "{%0,%1,%2,%3}, {%4,%5,%6,%7}, {%8,%9}, {%0,%1,%2,%3};"
        : "+f"(c[0]), "+f"(c[1]), "+f"(c[2]), "+f"(c[3])
        : "r"(a[0]), "r"(a[1]), "r"(a[2]), "r"(a[3]), "r"(b[0]), "r"(b[1]));
}
__device__ __forceinline__ uint32_t pack_bf16(float lo, float hi) {
    __nv_bfloat162 v = __floats2bfloat162_rn(lo, hi);
    return *reinterpret_cast<uint32_t*>(&v);
}

// ---------------------------------------------------------------------------
// Kernel 1: x_s = x @ Wx^T + bx  (unchanged — proven winner)
// M64 x N128 per CTA, 2 CTAs/SM, 782 CTAs.
// ---------------------------------------------------------------------------
__global__ __launch_bounds__(256, 2) void xs_kernel(
    const float* __restrict__ x, const float* __restrict__ Wx,
    const float* __restrict__ bx, int N)
{
    extern __shared__ float smem[];
    float* sW  = smem;                    // 128 x STX (tf32 bits)
    float* sA  = sW + 128 * STX;          // 64 x STX (tf32 bits)
    float* sbx = sA + 64 * STX;           // 128
    const int tid = threadIdx.x;
    const int tileBase = blockIdx.x * 64;

    for (int i = tid; i < 128 * 128; i += 256) {
        int d = i >> 7, e = i & 127;
        ((uint32_t*)sW)[d * STX + e] = f2tf32(Wx[i]);
    }
    for (int i = tid; i < 64 * 128; i += 256) {
        int r = i >> 7, e = i & 127;
        int node = tileBase + r;
        float v = (node < N) ? x[node * 128 + e] : 0.f;
        ((uint32_t*)sA)[r * STX + e] = f2tf32(v);
    }
    if (tid < 128) sbx[tid] = bx[tid];
    __syncthreads();

    const int w = tid >> 5, lane = tid & 31;
    const int lg = lane >> 2, lc = lane & 3;
    const int wm = w >> 2;    // 0..1
    const int wn = w & 3;     // 0..3

    float acc[2][4][4];
#pragma unroll
    for (int mi = 0; mi < 2; mi++)
#pragma unroll
        for (int ni = 0; ni < 4; ni++)
#pragma unroll
            for (int j = 0; j < 4; j++) acc[mi][ni][j] = 0.f;

    const uint32_t* uA = (const uint32_t*)sA;
    const uint32_t* uW = (const uint32_t*)sW;
#pragma unroll 4
    for (int ks = 0; ks < 16; ks++) {
        const int e0 = ks * 8;
        uint32_t afr[2][4];
#pragma unroll
        for (int mi = 0; mi < 2; mi++) {
            int r = wm * 32 + mi * 16 + lg;
            afr[mi][0] = uA[r * STX + e0 + lc];
            afr[mi][1] = uA[(r + 8) * STX + e0 + lc];
            afr[mi][2] = uA[r * STX + e0 + 4 + lc];
            afr[mi][3] = uA[(r + 8) * STX + e0 + 4 + lc];
        }
#pragma unroll
        for (int ni = 0; ni < 4; ni++) {
            int c0 = wn * 32 + ni * 8;
            uint32_t bfr[2];
            bfr[0] = uW[(c0 + lg) * STX + e0 + lc];
            bfr[1] = uW[(c0 + lg) * STX + e0 + 4 + lc];
            mma_tf32_frag(acc[0][ni], afr[0], bfr);
            mma_tf32_frag(acc[1][ni], afr[1], bfr);
        }
    }
#pragma unroll
    for (int mi = 0; mi < 2; mi++)
#pragma unroll
        for (int rh = 0; rh < 2; rh++) {
            int r = wm * 32 + mi * 16 + rh * 8 + lg;
            int node = tileBase + r;
            if (node < N) {
#pragma unroll
                for (int ni = 0; ni < 4; ni++)
#pragma unroll
                    for (int cc = 0; cc < 2; cc++) {
                        int d = wn * 32 + ni * 8 + 2 * lc + cc;
                        g_xs[node * 128 + d] = acc[mi][ni][rh * 2 + cc] + sbx[d];
                    }
            }
        }
}

// ---------------------------------------------------------------------------
// Main kernel: 4 CTAs/SM (64 regs, 53KB smem). XOR-swizzled sA/sB
// (phys = row*256 + (c ^ ((row&7)<<5))): conflict-free without padding.
// GEMM loads have row&7 == lg, so load addr = row*256 + ((ks<<5)^(lg<<5)) + 8*lc.
// scb folded into cxs at tile load; node == wm in scores (thread-constant).
// ---------------------------------------------------------------------------
#define SA_BYTES 16384           // 64 x 256B
#define SB_BYTES 32768           // 128 x 256B

__global__ __launch_bounds__(256, 4) void gnn_main_kernel(
    const float* __restrict__ x_nb, const float* __restrict__ weight,
    const float* __restrict__ Wn, const float* __restrict__ bn,
    const float* __restrict__ Ww, const float* __restrict__ bw,
    const float* __restrict__ Wl,
    float* __restrict__ out, int N, int numTiles)
{
    extern __shared__ char dsm[];
    char* sAb = dsm;                       // swizzled bf16 tile
    char* sBb = dsm + SA_BYTES;            // swizzled bf16 Wn
    float* cxs   = (float*)(dsm + SA_BYTES + SB_BYTES);  // 256: x_s + bn + bw
    float* swt   = cxs + 256;     // 64
    float* spart = swt + 64;      // 256
    float* sattn = spart + 256;   // 64
    float* scb   = sattn + 64;    // 128: bn + bw
    float* sWw   = scb + 128;     // 128
    float* sWl   = sWw + 128;     // 128

    const int tid  = threadIdx.x;
    const int w    = tid >> 5, lane = tid & 31;
    const int lg   = lane >> 2, lc = lane & 3;
    const int wm   = w >> 2;     // 0..1 (== node in scores)
    const int wn   = w & 3;      // 0..3
    const int lg5  = lg << 5;

    if (tid < 128) {
        scb[tid] = bn[tid] + bw[tid];
        sWw[tid] = Ww[tid];
        sWl[tid] = Wl[tid];
    }
    // One-time Wn -> swizzled smem bf16.
    for (int i = tid; i < 128 * 64; i += 256) {
        const int n = i >> 6, k2 = i & 63;
        const float2 v = ((const float2*)Wn)[i];
        const uint32_t coff = (uint32_t)(k2 * 4) ^ (uint32_t)((n & 7) << 5);
        *(uint32_t*)(sBb + n * 256 + coff) = pack_bf16(v.x, v.y);
    }
    __syncthreads();   // scb visible before first tile's cxs fold; sB ordered too

    const long rowMax = (long)N * 32 - 1;
    const long wMaxQ  = (long)N * 8 - 1;
    const int grid = gridDim.x;

    for (int t = blockIdx.x; t < numTiles; t += grid) {
        // ---- load tile: 64 rows x 128 fp32 -> swizzled bf16 smem (2 batches) ----
        {
            const long r0 = (long)t * 64;
#pragma unroll
            for (int half = 0; half < 2; half++) {
                float4 v[4];
#pragma unroll
                for (int u = 0; u < 4; u++) {
                    const int qi = tid + (half * 4 + u) * 256;
                    long gr = r0 + (qi >> 5);
                    if (gr > rowMax) gr = rowMax;
                    v[u] = __ldg((const float4*)x_nb + gr * 32 + (qi & 31));
                }
#pragma unroll
                for (int u = 0; u < 4; u++) {
                    const int qi = tid + (half * 4 + u) * 256;
                    const int row = qi >> 5, c8 = qi & 31;
                    uint2 p; p.x = pack_bf16(v[u].x, v[u].y); p.y = pack_bf16(v[u].z, v[u].w);
                    const uint32_t coff = (uint32_t)(c8 * 8) ^ (uint32_t)((row & 7) << 5);
                    *(uint2*)(sAb + row * 256 + coff) = p;
                }
            }
            if (tid < 64) {
                long node = (long)t * 2 + (tid >> 5); if (node > N - 1) node = N - 1;
                float4 xv = __ldg((const float4*)g_xs + node * 32 + (tid & 31));
                const float4 cb = ((const float4*)scb)[tid & 31];
                xv.x += cb.x; xv.y += cb.y; xv.z += cb.z; xv.w += cb.w;
                ((float4*)cxs)[tid] = xv;
            } else if (tid < 80) {
                const int j = tid - 64;
                long wi = (long)t * 16 + j; if (wi > wMaxQ) wi = wMaxQ;
                ((float4*)swt)[j] = __ldg((const float4*)weight + wi);
            }
        }
        __syncthreads();   // sync1: tile visible

        // ---- GEMM: warp M32 x N32, K=128 (physical-k-quad remap, proven) ----
        float acc[2][4][4];
#pragma unroll
        for (int mi = 0; mi < 2; mi++)
#pragma unroll
            for (int ni = 0; ni < 4; ni++)
#pragma unroll
                for (int j = 0; j < 4; j++) acc[mi][ni][j] = 0.f;

        const char* aBase = sAb + (wm * 32 + lg) * 256 + lc * 8;
        const char* bBase = sBb + (wn * 32 + lg) * 256 + lc * 8;
#pragma unroll
        for (int ks = 0; ks < 8; ks++) {
            const uint32_t koff = (uint32_t)(ks << 5) ^ (uint32_t)lg5;
            uint32_t a[2][4];
#pragma unroll
            for (int mi = 0; mi < 2; mi++) {
                const uint2 q0 = *(const uint2*)(aBase + mi * 4096 + koff);
                const uint2 q1 = *(const uint2*)(aBase + mi * 4096 + 2048 + koff);
                a[mi][0] = q0.x; a[mi][2] = q0.y;
                a[mi][1] = q1.x; a[mi][3] = q1.y;
            }
#pragma unroll
            for (int ni = 0; ni < 4; ni++) {
                const uint2 qb = *(const uint2*)(bBase + ni * 2048 + koff);
                uint32_t b[2] = {qb.x, qb.y};
                mma_bf16(acc[0][ni], a[0], b);
                mma_bf16(acc[1][ni], a[1], b);
            }
        }

        // ---- scores: h = n_s + cxs + weight*Ww ; leaky(0.1) ; dot Wl ----
#pragma unroll
        for (int mi = 0; mi < 2; mi++)
#pragma unroll
            for (int rh = 0; rh < 2; rh++) {
                const int r = wm * 32 + mi * 16 + rh * 8 + lg;   // 0..63
                const int k = r & 31;
                const float wgt = swt[wm * 32 + k];
                float p = 0.f;
#pragma unroll
                for (int ni = 0; ni < 4; ni++)
#pragma unroll
                    for (int cc = 0; cc < 2; cc++) {
                        const int d = wn * 32 + ni * 8 + 2 * lc + cc;
                        float h = acc[mi][ni][rh * 2 + cc]
                                + fmaf(wgt, sWw[d], cxs[wm * 128 + d]);
                        h = fmaxf(h, 0.f) + 0.1f * fminf(h, 0.f);
                        p = fmaf(sWl[d], h, p);
                    }
                p += __shfl_xor_sync(0xffffffffu, p, 1);
                p += __shfl_xor_sync(0xffffffffu, p, 2);
                if (lc == 0) spart[r * 4 + wn] = p;
            }
        __syncthreads();   // sync2: spart ready; sA/cxs/swt reads complete

        // ---- softmax over K=32 per node (bl dropped: softmax-invariant) ----
        if (w < 2) {
            const int r = w * 32 + lane;    // node = w, k = lane
            float s = spart[r * 4] + spart[r * 4 + 1] + spart[r * 4 + 2] + spart[r * 4 + 3];
            float m = s;
#pragma unroll
            for (int o = 16; o; o >>= 1) m = fmaxf(m, __shfl_xor_sync(0xffffffffu, m, o));
            float e = expf(s - m);
            float su = e;
#pragma unroll
            for (int o = 16; o; o >>= 1) su += __shfl_xor_sync(0xffffffffu, su, o);
            sattn[r] = e / su;
        }
        __syncthreads();   // sync3: sattn ready; spart reads complete

        // ---- output: out[n,d] = sum_k attn[k] * x_nb[n,k,d]  (fp32, L1-hot) ----
        {
            const int node = tid >> 7, d = tid & 127;
            const long gn = (long)t * 2 + node;
            if (gn < N) {
                const float* src = x_nb + (gn * 32) * 128 + d;
                const float* at  = sattn + node * 32;
                float s0 = 0.f, s1 = 0.f;
#pragma unroll
                for (int k = 0; k < 32; k += 2) {
                    s0 = fmaf(at[k],     __ldg(src + k * 128),       s0);
                    s1 = fmaf(at[k + 1], __ldg(src + (k + 1) * 128), s1);
                }
                out[gn * 128 + d] = s0 + s1;
            }
        }
    }
}

// ---------------------------------------------------------------------------
extern "C" void kernel_launch(void* const* d_in, const int* in_sizes, int n_in,
                              void* d_out, int out_size)
{
    const float* x      = (const float*)d_in[0];
    const float* x_nb   = (const float*)d_in[1];
    const float* weight = (const float*)d_in[2];
    const float* Wx     = (const float*)d_in[3];
    const float* bx     = (const float*)d_in[4];
    const float* Wn     = (const float*)d_in[5];
    const float* bn     = (const float*)d_in[6];
    const float* Ww     = (const float*)d_in[7];
    const float* bw     = (const float*)d_in[8];
    const float* Wl     = (const float*)d_in[9];
    // d_in[10] = bl: softmax-invariant, unused.
    float* out = (float*)d_out;

    const int N = in_sizes[0] / 128;

    const size_t smem1 = (size_t)(128 * STX + 64 * STX + 128) * sizeof(float);
    cudaFuncSetAttribute(xs_kernel, cudaFuncAttributeMaxDynamicSharedMemorySize, (int)smem1);

    const size_t smem2 = SA_BYTES + SB_BYTES
                       + (256 + 64 + 256 + 64 + 128 + 128 + 128) * sizeof(float);
    cudaFuncSetAttribute(gnn_main_kernel, cudaFuncAttributeMaxDynamicSharedMemorySize, (int)smem2);

    int nSM = 148;
    cudaDeviceGetAttribute(&nSM, cudaDevAttrMultiProcessorCount, 0);

    const int blocks1 = (N + 63) / 64;
    xs_kernel<<<blocks1, 256, smem1>>>(x, Wx, bx, N);

    const int numTiles = (N + 1) / 2;
    int grid = 4 * nSM;
    if (grid > numTiles) grid = numTiles;
    gnn_main_kernel<<<grid, 256, smem2>>>(x_nb, weight, Wn, bn, Ww, bw, Wl, out, N, numTiles);
}

// round 14
// speedup vs baseline: 1.1484x; 1.1484x over previous
#include <cuda_runtime.h>
#include <cuda_bf16.h>
#include <cstdint>

#define STX 132      // xs-kernel smem stride (proven)

// Scratch for x_s = x @ Wx^T + bx
__device__ float g_xs[65536 * 128];

__device__ __forceinline__ uint32_t f2tf32(float f) {
    uint32_t r; asm volatile("cvt.rna.tf32.f32 %0, %1;" : "=r"(r) : "f"(f)); return r;
}
__device__ __forceinline__ void mma_tf32_frag(float c[4], const uint32_t a[4], const uint32_t b[2]) {
    asm volatile(
        "mma.sync.aligned.m16n8k8.row.col.f32.tf32.tf32.f32 "
        "{%0,%1,%2,%3}, {%4,%5,%6,%7}, {%8,%9}, {%0,%1,%2,%3};"
        : "+f"(c[0]), "+f"(c[1]), "+f"(c[2]), "+f"(c[3])
        : "r"(a[0]), "r"(a[1]), "r"(a[2]), "r"(a[3]), "r"(b[0]), "r"(b[1]));
}
__device__ __forceinline__ void mma_bf16(float c[4], const uint32_t a[4], const uint32_t b[2]) {
    asm volatile(
        "mma.sync.aligned.m16n8k16.row.col.f32.bf16.bf16.f32 "
        "{%0,%1,%2,%3}, {%4,%5,%6,%7}, {%8,%9}, {%0,%1,%2,%3};"
        : "+f"(c[0]), "+f"(c[1]), "+f"(c[2]), "+f"(c[3])
        : "r"(a[0]), "r"(a[1]), "r"(a[2]), "r"(a[3]), "r"(b[0]), "r"(b[1]));
}
__device__ __forceinline__ uint32_t pack_bf16(float lo, float hi) {
    __nv_bfloat162 v = __floats2bfloat162_rn(lo, hi);
    return *reinterpret_cast<uint32_t*>(&v);
}

// ---------------------------------------------------------------------------
// Kernel 1: x_s = x @ Wx^T + bx  (unchanged — proven winner)
// M64 x N128 per CTA, 2 CTAs/SM, 782 CTAs.
// ---------------------------------------------------------------------------
__global__ __launch_bounds__(256, 2) void xs_kernel(
    const float* __restrict__ x, const float* __restrict__ Wx,
    const float* __restrict__ bx, int N)
{
    extern __shared__ float smem[];
    float* sW  = smem;                    // 128 x STX (tf32 bits)
    float* sA  = sW + 128 * STX;          // 64 x STX (tf32 bits)
    float* sbx = sA + 64 * STX;           // 128
    const int tid = threadIdx.x;
    const int tileBase = blockIdx.x * 64;

    for (int i = tid; i < 128 * 128; i += 256) {
        int d = i >> 7, e = i & 127;
        ((uint32_t*)sW)[d * STX + e] = f2tf32(Wx[i]);
    }
    for (int i = tid; i < 64 * 128; i += 256) {
        int r = i >> 7, e = i & 127;
        int node = tileBase + r;
        float v = (node < N) ? x[node * 128 + e] : 0.f;
        ((uint32_t*)sA)[r * STX + e] = f2tf32(v);
    }
    if (tid < 128) sbx[tid] = bx[tid];
    __syncthreads();

    const int w = tid >> 5, lane = tid & 31;
    const int lg = lane >> 2, lc = lane & 3;
    const int wm = w >> 2;    // 0..1
    const int wn = w & 3;     // 0..3

    float acc[2][4][4];
#pragma unroll
    for (int mi = 0; mi < 2; mi++)
#pragma unroll
        for (int ni = 0; ni < 4; ni++)
#pragma unroll
            for (int j = 0; j < 4; j++) acc[mi][ni][j] = 0.f;

    const uint32_t* uA = (const uint32_t*)sA;
    const uint32_t* uW = (const uint32_t*)sW;
#pragma unroll 4
    for (int ks = 0; ks < 16; ks++) {
        const int e0 = ks * 8;
        uint32_t afr[2][4];
#pragma unroll
        for (int mi = 0; mi < 2; mi++) {
            int r = wm * 32 + mi * 16 + lg;
            afr[mi][0] = uA[r * STX + e0 + lc];
            afr[mi][1] = uA[(r + 8) * STX + e0 + lc];
            afr[mi][2] = uA[r * STX + e0 + 4 + lc];
            afr[mi][3] = uA[(r + 8) * STX + e0 + 4 + lc];
        }
#pragma unroll
        for (int ni = 0; ni < 4; ni++) {
            int c0 = wn * 32 + ni * 8;
            uint32_t bfr[2];
            bfr[0] = uW[(c0 + lg) * STX + e0 + lc];
            bfr[1] = uW[(c0 + lg) * STX + e0 + 4 + lc];
            mma_tf32_frag(acc[0][ni], afr[0], bfr);
            mma_tf32_frag(acc[1][ni], afr[1], bfr);
        }
    }
#pragma unroll
    for (int mi = 0; mi < 2; mi++)
#pragma unroll
        for (int rh = 0; rh < 2; rh++) {
            int r = wm * 32 + mi * 16 + rh * 8 + lg;
            int node = tileBase + r;
            if (node < N) {
#pragma unroll
                for (int ni = 0; ni < 4; ni++)
#pragma unroll
                    for (int cc = 0; cc < 2; cc++) {
                        int d = wn * 32 + ni * 8 + 2 * lc + cc;
                        g_xs[node * 128 + d] = acc[mi][ni][rh * 2 + cc] + sbx[d];
                    }
            }
        }
}

// ---------------------------------------------------------------------------
// Main kernel: 3 CTAs/SM (reverted from 4 — the 64-reg cap cost more per-warp
// ILP than the 4th CTA added; measured 401 vs 360 us). Keeps round-12/13
// improvements: XOR-swizzled sA/sB (53KB, no padding), scb folded into cxs,
// node==wm simplification. GEMM loads: row&7 == lg, so
// addr = row*256 + ((ks<<5)^(lg<<5)) + 8*lc.
// ---------------------------------------------------------------------------
#define SA_BYTES 16384           // 64 x 256B
#define SB_BYTES 32768           // 128 x 256B

__global__ __launch_bounds__(256, 3) void gnn_main_kernel(
    const float* __restrict__ x_nb, const float* __restrict__ weight,
    const float* __restrict__ Wn, const float* __restrict__ bn,
    const float* __restrict__ Ww, const float* __restrict__ bw,
    const float* __restrict__ Wl,
    float* __restrict__ out, int N, int numTiles)
{
    extern __shared__ char dsm[];
    char* sAb = dsm;                       // swizzled bf16 tile
    char* sBb = dsm + SA_BYTES;            // swizzled bf16 Wn
    float* cxs   = (float*)(dsm + SA_BYTES + SB_BYTES);  // 256: x_s + bn + bw
    float* swt   = cxs + 256;     // 64
    float* spart = swt + 64;      // 256
    float* sattn = spart + 256;   // 64
    float* scb   = sattn + 64;    // 128: bn + bw
    float* sWw   = scb + 128;     // 128
    float* sWl   = sWw + 128;     // 128

    const int tid  = threadIdx.x;
    const int w    = tid >> 5, lane = tid & 31;
    const int lg   = lane >> 2, lc = lane & 3;
    const int wm   = w >> 2;     // 0..1 (== node in scores)
    const int wn   = w & 3;      // 0..3
    const int lg5  = lg << 5;

    if (tid < 128) {
        scb[tid] = bn[tid] + bw[tid];
        sWw[tid] = Ww[tid];
        sWl[tid] = Wl[tid];
    }
    // One-time Wn -> swizzled smem bf16.
    for (int i = tid; i < 128 * 64; i += 256) {
        const int n = i >> 6, k2 = i & 63;
        const float2 v = ((const float2*)Wn)[i];
        const uint32_t coff = (uint32_t)(k2 * 4) ^ (uint32_t)((n & 7) << 5);
        *(uint32_t*)(sBb + n * 256 + coff) = pack_bf16(v.x, v.y);
    }
    __syncthreads();   // scb visible before first tile's cxs fold; sB ordered too

    const long rowMax = (long)N * 32 - 1;
    const long wMaxQ  = (long)N * 8 - 1;
    const int grid = gridDim.x;

    for (int t = blockIdx.x; t < numTiles; t += grid) {
        // ---- load tile: 64 rows x 128 fp32 -> swizzled bf16 smem ----
        {
            const long r0 = (long)t * 64;
            float4 v[8];
#pragma unroll
            for (int u = 0; u < 8; u++) {
                const int qi = tid + u * 256;
                long gr = r0 + (qi >> 5);
                if (gr > rowMax) gr = rowMax;
                v[u] = __ldg((const float4*)x_nb + gr * 32 + (qi & 31));
            }
#pragma unroll
            for (int u = 0; u < 8; u++) {
                const int qi = tid + u * 256;
                const int row = qi >> 5, c8 = qi & 31;
                uint2 p; p.x = pack_bf16(v[u].x, v[u].y); p.y = pack_bf16(v[u].z, v[u].w);
                const uint32_t coff = (uint32_t)(c8 * 8) ^ (uint32_t)((row & 7) << 5);
                *(uint2*)(sAb + row * 256 + coff) = p;
            }
            if (tid < 64) {
                long node = (long)t * 2 + (tid >> 5); if (node > N - 1) node = N - 1;
                float4 xv = __ldg((const float4*)g_xs + node * 32 + (tid & 31));
                const float4 cb = ((const float4*)scb)[tid & 31];
                xv.x += cb.x; xv.y += cb.y; xv.z += cb.z; xv.w += cb.w;
                ((float4*)cxs)[tid] = xv;
            } else if (tid < 80) {
                const int j = tid - 64;
                long wi = (long)t * 16 + j; if (wi > wMaxQ) wi = wMaxQ;
                ((float4*)swt)[j] = __ldg((const float4*)weight + wi);
            }
        }
        __syncthreads();   // sync1: tile visible

        // ---- GEMM: warp M32 x N32, K=128 (physical-k-quad remap, proven) ----
        float acc[2][4][4];
#pragma unroll
        for (int mi = 0; mi < 2; mi++)
#pragma unroll
            for (int ni = 0; ni < 4; ni++)
#pragma unroll
                for (int j = 0; j < 4; j++) acc[mi][ni][j] = 0.f;

        const char* aBase = sAb + (wm * 32 + lg) * 256 + lc * 8;
        const char* bBase = sBb + (wn * 32 + lg) * 256 + lc * 8;
#pragma unroll
        for (int ks = 0; ks < 8; ks++) {
            const uint32_t koff = (uint32_t)(ks << 5) ^ (uint32_t)lg5;
            uint32_t a[2][4];
#pragma unroll
            for (int mi = 0; mi < 2; mi++) {
                const uint2 q0 = *(const uint2*)(aBase + mi * 4096 + koff);
                const uint2 q1 = *(const uint2*)(aBase + mi * 4096 + 2048 + koff);
                a[mi][0] = q0.x; a[mi][2] = q0.y;
                a[mi][1] = q1.x; a[mi][3] = q1.y;
            }
#pragma unroll
            for (int ni = 0; ni < 4; ni++) {
                const uint2 qb = *(const uint2*)(bBase + ni * 2048 + koff);
                uint32_t b[2] = {qb.x, qb.y};
                mma_bf16(acc[0][ni], a[0], b);
                mma_bf16(acc[1][ni], a[1], b);
            }
        }

        // ---- scores: h = n_s + cxs + weight*Ww ; leaky(0.1) ; dot Wl ----
#pragma unroll
        for (int mi = 0; mi < 2; mi++)
#pragma unroll
            for (int rh = 0; rh < 2; rh++) {
                const int r = wm * 32 + mi * 16 + rh * 8 + lg;   // 0..63
                const int k = r & 31;
                const float wgt = swt[wm * 32 + k];
                float p = 0.f;
#pragma unroll
                for (int ni = 0; ni < 4; ni++)
#pragma unroll
                    for (int cc = 0; cc < 2; cc++) {
                        const int d = wn * 32 + ni * 8 + 2 * lc + cc;
                        float h = acc[mi][ni][rh * 2 + cc]
                                + fmaf(wgt, sWw[d], cxs[wm * 128 + d]);
                        h = fmaxf(h, 0.f) + 0.1f * fminf(h, 0.f);
                        p = fmaf(sWl[d], h, p);
                    }
                p += __shfl_xor_sync(0xffffffffu, p, 1);
                p += __shfl_xor_sync(0xffffffffu, p, 2);
                if (lc == 0) spart[r * 4 + wn] = p;
            }
        __syncthreads();   // sync2: spart ready; sA/cxs/swt reads complete

        // ---- softmax over K=32 per node (bl dropped: softmax-invariant) ----
        if (w < 2) {
            const int r = w * 32 + lane;    // node = w, k = lane
            float s = spart[r * 4] + spart[r * 4 + 1] + spart[r * 4 + 2] + spart[r * 4 + 3];
            float m = s;
#pragma unroll
            for (int o = 16; o; o >>= 1) m = fmaxf(m, __shfl_xor_sync(0xffffffffu, m, o));
            float e = expf(s - m);
            float su = e;
#pragma unroll
            for (int o = 16; o; o >>= 1) su += __shfl_xor_sync(0xffffffffu, su, o);
            sattn[r] = e / su;
        }
        __syncthreads();   // sync3: sattn ready; spart reads complete

        // ---- output: out[n,d] = sum_k attn[k] * x_nb[n,k,d]  (fp32, L1-hot) ----
        {
            const int node = tid >> 7, d = tid & 127;
            const long gn = (long)t * 2 + node;
            if (gn < N) {
                const float* src = x_nb + (gn * 32) * 128 + d;
                const float* at  = sattn + node * 32;
                float s0 = 0.f, s1 = 0.f;
#pragma unroll
                for (int k = 0; k < 32; k += 2) {
                    s0 = fmaf(at[k],     __ldg(src + k * 128),       s0);
                    s1 = fmaf(at[k + 1], __ldg(src + (k + 1) * 128), s1);
                }
                out[gn * 128 + d] = s0 + s1;
            }
        }
    }
}

// ---------------------------------------------------------------------------
extern "C" void kernel_launch(void* const* d_in, const int* in_sizes, int n_in,
                              void* d_out, int out_size)
{
    const float* x      = (const float*)d_in[0];
    const float* x_nb   = (const float*)d_in[1];
    const float* weight = (const float*)d_in[2];
    const float* Wx     = (const float*)d_in[3];
    const float* bx     = (const float*)d_in[4];
    const float* Wn     = (const float*)d_in[5];
    const float* bn     = (const float*)d_in[6];
    const float* Ww     = (const float*)d_in[7];
    const float* bw     = (const float*)d_in[8];
    const float* Wl     = (const float*)d_in[9];
    // d_in[10] = bl: softmax-invariant, unused.
    float* out = (float*)d_out;

    const int N = in_sizes[0] / 128;

    const size_t smem1 = (size_t)(128 * STX + 64 * STX + 128) * sizeof(float);
    cudaFuncSetAttribute(xs_kernel, cudaFuncAttributeMaxDynamicSharedMemorySize, (int)smem1);

    const size_t smem2 = SA_BYTES + SB_BYTES
                       + (256 + 64 + 256 + 64 + 128 + 128 + 128) * sizeof(float);
    cudaFuncSetAttribute(gnn_main_kernel, cudaFuncAttributeMaxDynamicSharedMemorySize, (int)smem2);

    int nSM = 148;
    cudaDeviceGetAttribute(&nSM, cudaDevAttrMultiProcessorCount, 0);

    const int blocks1 = (N + 63) / 64;
    xs_kernel<<<blocks1, 256, smem1>>>(x, Wx, bx, N);

    const int numTiles = (N + 1) / 2;
    int grid = 3 * nSM;
    if (grid > numTiles) grid = numTiles;
    gnn_main_kernel<<<grid, 256, smem2>>>(x_nb, weight, Wn, bn, Ww, bw, Wl, out, N, numTiles);
}